// round 12
// baseline (speedup 1.0000x reference)
#include <cuda_runtime.h>
#include <cuda_bf16.h>
#include <math.h>
#include <stdint.h>

#define B_ 256
#define L_ 512
#define H_ 1024
#define S_ 16
#define HOR_ 64
#define PRED_ELEMS (B_*HOR_*L_)

typedef __nv_bfloat16 bf16;

// ---------------- fp32 scratch ----------------------------------------------
__device__ float g_q[B_*H_];
__device__ float g_kmem[S_*H_];
__device__ float g_vmem[S_*H_];
__device__ float g_ctx[B_*H_];
__device__ float g_context[B_*L_];
__device__ float g_pgh[B_*H_];
__device__ float g_prior[B_*L_];
__device__ float g_c0[B_*H_];
__device__ float g_c1[B_*H_];

// ---------------- bf16 split scratch ----------------------------------------
__device__ __align__(16) bf16 g_xh[B_*L_],  g_xl[B_*L_];
__device__ __align__(16) bf16 g_h0h[2][B_*H_], g_h0l[2][B_*H_];
__device__ __align__(16) bf16 g_h1h[2][B_*H_], g_h1l[2][B_*H_];
__device__ __align__(16) bf16 g_th[B_*H_],  g_tl[B_*H_];
__device__ __align__(16) bf16 g_wih0h[4*H_*L_], g_wih0l[4*H_*L_];
__device__ __align__(16) bf16 g_whh0h[4*H_*H_], g_whh0l[4*H_*H_];
__device__ __align__(16) bf16 g_wih1h[4*H_*H_], g_wih1l[4*H_*H_];
__device__ __align__(16) bf16 g_whh1h[4*H_*H_], g_whh1l[4*H_*H_];
__device__ __align__(16) bf16 g_opW1h[H_*H_],   g_opW1l[H_*H_];
__device__ __align__(16) bf16 g_opW2h[L_*H_],   g_opW2l[L_*H_];

// ---------------- hierarchical grid barrier (128 CTAs: 4 x 32) ---------------
__device__ unsigned g_cnt[4*32];
__device__ unsigned g_cnt2 = 0;
__device__ unsigned g_gen  = 0;

// ---------------- low-level helpers ------------------------------------------
__device__ __forceinline__ uint32_t smem_u32(const void* p) {
    uint32_t a;
    asm("{ .reg .u64 t; cvta.to.shared.u64 t, %1; cvt.u32.u64 %0, t; }" : "=r"(a) : "l"(p));
    return a;
}

#define CP_ASYNC16(d, s) \
    asm volatile("cp.async.cg.shared.global [%0], [%1], 16;" :: "r"(d), "l"(s))
#define CP_COMMIT()  asm volatile("cp.async.commit_group;" ::: "memory")

__device__ __forceinline__ void ldm_x4(uint32_t* r, uint32_t addr) {
    asm volatile("ldmatrix.sync.aligned.m8n8.x4.shared.b16 {%0,%1,%2,%3}, [%4];"
                 : "=r"(r[0]), "=r"(r[1]), "=r"(r[2]), "=r"(r[3]) : "r"(addr));
}

__device__ __forceinline__ void mma16816(float* d, const uint32_t* a, const uint32_t* b) {
    asm volatile(
        "mma.sync.aligned.m16n8k16.row.col.f32.bf16.bf16.f32 "
        "{%0,%1,%2,%3}, {%4,%5,%6,%7}, {%8,%9}, {%0,%1,%2,%3};"
        : "+f"(d[0]), "+f"(d[1]), "+f"(d[2]), "+f"(d[3])
        : "r"(a[0]), "r"(a[1]), "r"(a[2]), "r"(a[3]), "r"(b[0]), "r"(b[1]));
}

__device__ __forceinline__ void grid_sync() {
    __syncthreads();
    if (threadIdx.x == 0) {
        volatile unsigned* genp = (volatile unsigned*)&g_gen;
        const unsigned gen = *genp;
        __threadfence();
        unsigned old = atomicAdd(&g_cnt[(blockIdx.x & 3) * 32], 1u);
        bool flipped = false;
        if (old == 31u) {
            unsigned old2 = atomicAdd(&g_cnt2, 1u);
            if (old2 == 3u) {
                #pragma unroll
                for (int i = 0; i < 4; i++) g_cnt[i * 32] = 0u;
                g_cnt2 = 0u;
                __threadfence();
                *genp = gen + 1u;
                flipped = true;
            }
        }
        if (!flipped) {
            while (*genp == gen) { }
        }
        __threadfence();
    }
    __syncthreads();
}

// ---------------- device GEMM core (dual source, templated warp grid) --------
#define PSTRIDE 40
#define P_SMEM (3 * (2*(128+64)) * PSTRIDE * 2)   // 92160 (gates config)

// acc += A1@W1^T + A2@W2^T  (bf16x3 split). 3-stage cp.async, 1 barrier/chunk.
template<int BM, int BN, int NWM, int NWN>
__device__ __forceinline__ void gemm_dual(
    uint32_t sb, int tid,
    const bf16* __restrict__ Ah1, const bf16* __restrict__ Al1, int lda1,
    const bf16* __restrict__ Wh1, const bf16* __restrict__ Wl1, int ldw1, int nc1,
    const bf16* __restrict__ Ah2, const bf16* __restrict__ Al2, int lda2,
    const bf16* __restrict__ Wh2, const bf16* __restrict__ Wl2, int ldw2, int nc2,
    float (&acc)[(BM/NWM)/16][2*((BN/NWN)/16)][4])
{
    constexpr int NT  = 32 * NWM * NWN;
    constexpr int WM  = BM / NWM;
    constexpr int WN  = BN / NWN;
    constexpr int MI  = WM / 16;
    constexpr int NJ  = WN / 16;
    constexpr int AHo = 0;
    constexpr int ALo = BM * PSTRIDE;
    constexpr int WHo = 2 * BM * PSTRIDE;
    constexpr int WLo = (2 * BM + BN) * PSTRIDE;
    constexpr int STAGE_B = 2 * (BM + BN) * PSTRIDE * 2;

    const int lane = tid & 31, wid = tid >> 5;
    const int warp_m = wid / NWN, warp_n = wid % NWN;
    const int nc = nc1 + nc2;

    auto do_load = [&](int c) {
        const int src = (c < nc1) ? 0 : 1;
        const int k0  = ((src == 0) ? c : (c - nc1)) << 5;
        const bf16* Ah = src ? Ah2 : Ah1;
        const bf16* Al = src ? Al2 : Al1;
        const bf16* Wh = src ? Wh2 : Wh1;
        const bf16* Wl = src ? Wl2 : Wl1;
        const int lda = src ? lda2 : lda1;
        const int ldw = src ? ldw2 : ldw1;
        const uint32_t st = sb + (uint32_t)(c % 3) * STAGE_B;

        constexpr int T16 = 2 * (BM + BN) * 4;
        #pragma unroll
        for (int it = 0; it < T16 / NT; it++) {
            int idx = tid + it * NT;
            int row = idx >> 2, ch = idx & 3;
            const bf16* g; int soff;
            if (row < BM)             {               g = Ah + (size_t)row * lda; soff = AHo + row * PSTRIDE; }
            else if (row < 2*BM)      { int r = row - BM;   g = Al + (size_t)r * lda; soff = ALo + r * PSTRIDE; }
            else if (row < 2*BM + BN) { int r = row - 2*BM; g = Wh + (size_t)r * ldw; soff = WHo + r * PSTRIDE; }
            else                      { int r = row - 2*BM - BN; g = Wl + (size_t)r * ldw; soff = WLo + r * PSTRIDE; }
            CP_ASYNC16(st + (uint32_t)(soff + ch * 8) * 2, g + k0 + ch * 8);
        }
        CP_COMMIT();
    };

    do_load(0);
    if (nc > 1) do_load(1);

    const int a_row = warp_m * WM + (lane & 15);
    const int a_kof = (lane >> 4) << 3;
    const int b_row = warp_n * WN + ((lane >> 4) << 3) + (lane & 7);
    const int b_kof = ((lane >> 3) & 1) << 3;

    for (int c = 0; c < nc; c++) {
        if (c + 1 < nc) asm volatile("cp.async.wait_group 1;" ::: "memory");
        else            asm volatile("cp.async.wait_group 0;" ::: "memory");
        __syncthreads();

        if (c + 2 < nc) do_load(c + 2);

        const uint32_t st = sb + (uint32_t)(c % 3) * STAGE_B;

        #pragma unroll
        for (int k16 = 0; k16 < 2; k16++) {
            const int kk = k16 * 16;
            uint32_t ah[MI][4], al[MI][4], bh[NJ][4], bl[NJ][4];
            #pragma unroll
            for (int mi = 0; mi < MI; mi++) {
                ldm_x4(ah[mi], st + (uint32_t)((AHo + (a_row + mi*16) * PSTRIDE + kk + a_kof) * 2));
                ldm_x4(al[mi], st + (uint32_t)((ALo + (a_row + mi*16) * PSTRIDE + kk + a_kof) * 2));
            }
            #pragma unroll
            for (int g = 0; g < NJ; g++) {
                ldm_x4(bh[g], st + (uint32_t)((WHo + (b_row + g*16) * PSTRIDE + kk + b_kof) * 2));
                ldm_x4(bl[g], st + (uint32_t)((WLo + (b_row + g*16) * PSTRIDE + kk + b_kof) * 2));
            }
            #pragma unroll
            for (int mi = 0; mi < MI; mi++)
                #pragma unroll
                for (int nj = 0; nj < 2*NJ; nj++) {
                    const int g = nj >> 1, o = (nj & 1) * 2;
                    mma16816(acc[mi][nj], ah[mi], &bh[g][o]);
                    mma16816(acc[mi][nj], al[mi], &bh[g][o]);
                    mma16816(acc[mi][nj], ah[mi], &bl[g][o]);
                }
        }
    }
    __syncthreads();
}

template<int MI, int NJ2>
__device__ __forceinline__ void zero_acc(float (&acc)[MI][NJ2][4]) {
    #pragma unroll
    for (int i = 0; i < MI; i++)
        #pragma unroll
        for (int j = 0; j < NJ2; j++)
            #pragma unroll
            for (int r = 0; r < 4; r++) acc[i][j][r] = 0.f;
}

// fused LSTM cell epilogue; warp grid NWMxNWN, warp tile 32x32 (MI=2,NJ=2).
template<int NWN>
__device__ __forceinline__ void cell_epi(
    float (&acc)[2][4][4], int tid, int m0, int n0,
    const float* __restrict__ b1, const float* __restrict__ b2,
    const float* __restrict__ cin, float* __restrict__ cout,
    bf16* __restrict__ Oh, bf16* __restrict__ Ol)
{
    const int lane = tid & 31, wid = tid >> 5;
    const int warp_m = wid / NWN, warp_n = wid % NWN;
    const int m_base = m0 + warp_m * 32;
    const int n_base = n0 + warp_n * 32;
    #pragma unroll
    for (int mi = 0; mi < 2; mi++) {
        #pragma unroll
        for (int nj = 0; nj < 4; nj++) {
            const int c0 = n_base + nj * 8 + (lane & 3) * 2;
            const int bi0 = (c0 & 3) * H_ + (c0 >> 2);
            const int bi1 = ((c0 + 1) & 3) * H_ + ((c0 + 1) >> 2);
            const float bias0 = b1[bi0] + b2[bi0];
            const float bias1 = b1[bi1] + b2[bi1];
            #pragma unroll
            for (int half = 0; half < 2; half++) {
                const int row = m_base + mi * 16 + (lane >> 2) + half * 8;
                float v0 = acc[mi][nj][half*2 + 0] + bias0;
                float v1 = acc[mi][nj][half*2 + 1] + bias1;
                float p0 = __shfl_xor_sync(0xffffffffu, v0, 1);
                float p1 = __shfl_xor_sync(0xffffffffu, v1, 1);
                if ((lane & 1) == 0) {
                    const int j   = c0 >> 2;
                    const int idx = row * H_ + j;
                    float ig = 1.f / (1.f + expf(-v0));
                    float fg = 1.f / (1.f + expf(-v1));
                    float gg = tanhf(p0);
                    float og = 1.f / (1.f + expf(-p1));
                    float cv = fg * cin[idx] + ig * gg;
                    float hv = og * tanhf(cv);
                    cout[idx] = cv;
                    bf16 hb = __float2bfloat16(hv);
                    Oh[idx] = hb;
                    Ol[idx] = __float2bfloat16(hv - __bfloat162float(hb));
                }
            }
        }
    }
}

// standard epilogue: bias (+relu), optional fp32 C, optional bf16 hi/lo split
template<int MI, int NJ, int NWN>
__device__ __forceinline__ void std_epi(
    float (&acc)[MI][2*NJ][4], int tid, int m0, int n0,
    const float* __restrict__ b,
    float* __restrict__ C, int ldc,
    bf16* __restrict__ Oh, bf16* __restrict__ Ol, int ldo, int relu)
{
    const int lane = tid & 31, wid = tid >> 5;
    const int warp_m = wid / NWN, warp_n = wid % NWN;
    const int m_base = m0 + warp_m * (MI * 16);
    const int n_base = n0 + warp_n * (NJ * 16);
    #pragma unroll
    for (int mi = 0; mi < MI; mi++) {
        #pragma unroll
        for (int nj = 0; nj < 2*NJ; nj++) {
            const int col = n_base + nj * 8 + (lane & 3) * 2;
            const float bias0 = b[col];
            const float bias1 = b[col + 1];
            #pragma unroll
            for (int half = 0; half < 2; half++) {
                const int row = m_base + mi * 16 + (lane >> 2) + half * 8;
                float v0 = acc[mi][nj][half*2 + 0] + bias0;
                float v1 = acc[mi][nj][half*2 + 1] + bias1;
                if (relu) { v0 = fmaxf(v0, 0.f); v1 = fmaxf(v1, 0.f); }
                if (C)
                    *reinterpret_cast<float2*>(C + (size_t)row * ldc + col) =
                        make_float2(v0, v1);
                if (Oh) {
                    bf16 h0 = __float2bfloat16(v0);
                    bf16 h1 = __float2bfloat16(v1);
                    bf16 l0 = __float2bfloat16(v0 - __bfloat162float(h0));
                    bf16 l1 = __float2bfloat16(v1 - __bfloat162float(h1));
                    bf16 hp[2] = {h0, h1}, lp[2] = {l0, l1};
                    *reinterpret_cast<uint32_t*>(Oh + (size_t)row * ldo + col) =
                        *reinterpret_cast<uint32_t*>(hp);
                    *reinterpret_cast<uint32_t*>(Ol + (size_t)row * ldo + col) =
                        *reinterpret_cast<uint32_t*>(lp);
                }
            }
        }
    }
}

// ---------------- persistent rollout kernel ----------------------------------
// 128 CTAs x 256 threads (8 warps).
__global__ void __launch_bounds__(256)
rollout_kernel(const float* __restrict__ bih0, const float* __restrict__ bhh0,
               const float* __restrict__ bih1, const float* __restrict__ bhh1,
               const float* __restrict__ opb1, const float* __restrict__ opb2,
               float* __restrict__ out)
{
    extern __shared__ __align__(16) char smem[];
    const uint32_t sb = smem_u32(smem);
    const int tid = threadIdx.x;
    const int cta = blockIdx.x;

    // gates mapping: 2 m-tiles x 64 n-tiles (tile 128x64)
    const int gm0 = (cta & 1) * 128;
    const int gn0 = (cta >> 1) * 64;
    // op1 mapping: 8 m-tiles x 16 n-tiles (tile 32x64)
    const int o1m = (cta & 7) * 32;
    const int o1n = (cta >> 3) * 64;
    // op2 mapping: 8 m-tiles x 8 n-tiles (tile 32x64), CTAs 0..63 active
    const int o2m = (cta & 7) * 32;
    const int o2n = (cta >> 3) * 64;

    for (int s = 0; s < HOR_; s++) {
        const int p = s & 1, pn = p ^ 1;

        // ---- phase 1: gates0 (x@wih0 + h0@whh0) + cell -> h0[pn], c0 ----
        {
            float acc[2][4][4];
            zero_acc(acc);
            gemm_dual<128,64,4,2>(sb, tid,
                g_xh + (size_t)gm0*L_, g_xl + (size_t)gm0*L_, L_,
                g_wih0h + (size_t)gn0*L_, g_wih0l + (size_t)gn0*L_, L_, L_/32,
                g_h0h[p] + (size_t)gm0*H_, g_h0l[p] + (size_t)gm0*H_, H_,
                g_whh0h + (size_t)gn0*H_, g_whh0l + (size_t)gn0*H_, H_, H_/32,
                acc);
            cell_epi<2>(acc, tid, gm0, gn0, bih0, bhh0, g_c0, g_c0, g_h0h[pn], g_h0l[pn]);
        }
        grid_sync();

        // ---- phase 2: gates1 (h0@wih1 + h1@whh1) + cell -> h1[pn], c1 ----
        {
            float acc[2][4][4];
            zero_acc(acc);
            gemm_dual<128,64,4,2>(sb, tid,
                g_h0h[pn] + (size_t)gm0*H_, g_h0l[pn] + (size_t)gm0*H_, H_,
                g_wih1h + (size_t)gn0*H_, g_wih1l + (size_t)gn0*H_, H_, H_/32,
                g_h1h[p] + (size_t)gm0*H_, g_h1l[p] + (size_t)gm0*H_, H_,
                g_whh1h + (size_t)gn0*H_, g_whh1l + (size_t)gn0*H_, H_, H_/32,
                acc);
            cell_epi<2>(acc, tid, gm0, gn0, bih1, bhh1, g_c1, g_c1, g_h1h[pn], g_h1l[pn]);
        }
        grid_sync();

        // ---- phase 3: op1 = relu(h1 @ opW1^T + b1) -> th/tl (32x64, 128 CTAs)
        {
            float acc[1][2][4];
            zero_acc(acc);
            gemm_dual<32,64,2,4>(sb, tid,
                g_h1h[pn] + (size_t)o1m*H_, g_h1l[pn] + (size_t)o1m*H_, H_,
                g_opW1h + (size_t)o1n*H_, g_opW1l + (size_t)o1n*H_, H_, H_/32,
                nullptr, nullptr, 0, nullptr, nullptr, 0, 0,
                acc);
            std_epi<1,1,4>(acc, tid, o1m, o1n, opb1, nullptr, 0, g_th, g_tl, H_, 1);
        }
        grid_sync();

        // ---- phase 4: op2 = t @ opW2^T + b2 -> out + x split (32x64, 64 CTAs)
        if (cta < 64) {
            float acc[1][2][4];
            zero_acc(acc);
            gemm_dual<32,64,2,4>(sb, tid,
                g_th + (size_t)o2m*H_, g_tl + (size_t)o2m*H_, H_,
                g_opW2h + (size_t)o2n*H_, g_opW2l + (size_t)o2n*H_, H_, H_/32,
                nullptr, nullptr, 0, nullptr, nullptr, 0, 0,
                acc);
            std_epi<1,1,4>(acc, tid, o2m, o2n, opb2,
                           out + (size_t)s * L_, HOR_*L_, g_xh, g_xl, L_, 0);
        }
        grid_sync();
    }
}

// ---------------- fp32 GEMM (prologue only) ---------------------------------
template<int BM,int BN,int BK,int TM,int TN,int NT>
__global__ __launch_bounds__(NT)
void gemm2_kernel(const float* __restrict__ A1, int lda1,
                  const float* __restrict__ W1, int ldw1, int K1,
                  const float* __restrict__ A2, int lda2,
                  const float* __restrict__ W2, int ldw2, int K2,
                  const float* __restrict__ b1, const float* __restrict__ b2,
                  float* __restrict__ C, int ldc, int M, int N, int relu)
{
    __shared__ __align__(16) float As[BK][BM+4];
    __shared__ __align__(16) float Ws[BK][BN+4];
    const int tid = threadIdx.x;
    const int m0  = blockIdx.y * BM;
    const int n0  = blockIdx.x * BN;
    const int m0t = (tid / (BN/TN)) * TM;
    const int n0t = (tid % (BN/TN)) * TN;
    float acc[TM][TN];
    #pragma unroll
    for (int i = 0; i < TM; i++)
        #pragma unroll
        for (int j = 0; j < TN; j++) acc[i][j] = 0.f;
    for (int src = 0; src < 2; src++) {
        const float* A = src ? A2 : A1;
        if (A == nullptr) break;
        const float* W = src ? W2 : W1;
        const int lda = src ? lda2 : lda1;
        const int ldw = src ? ldw2 : ldw1;
        const int K   = src ? K2   : K1;
        for (int k0 = 0; k0 < K; k0 += BK) {
            constexpr int A4 = BM*BK/4;
            #pragma unroll
            for (int it = 0; it < A4/NT; it++) {
                int i4 = tid + NT*it;
                int row = i4 / (BK/4), cv = i4 % (BK/4);
                float4 val = make_float4(0,0,0,0);
                int gr = m0 + row;
                if (gr < M) val = *reinterpret_cast<const float4*>(A + (size_t)gr*lda + k0 + cv*4);
                As[cv*4+0][row]=val.x; As[cv*4+1][row]=val.y;
                As[cv*4+2][row]=val.z; As[cv*4+3][row]=val.w;
            }
            constexpr int W4 = BN*BK/4;
            #pragma unroll
            for (int it = 0; it < W4/NT; it++) {
                int i4 = tid + NT*it;
                int row = i4 / (BK/4), cv = i4 % (BK/4);
                float4 val = *reinterpret_cast<const float4*>(W + (size_t)(n0+row)*ldw + k0 + cv*4);
                Ws[cv*4+0][row]=val.x; Ws[cv*4+1][row]=val.y;
                Ws[cv*4+2][row]=val.z; Ws[cv*4+3][row]=val.w;
            }
            __syncthreads();
            #pragma unroll
            for (int kk = 0; kk < BK; kk++) {
                float a[TM], bb[TN];
                #pragma unroll
                for (int i = 0; i < TM; i += 4) {
                    float4 t = *reinterpret_cast<const float4*>(&As[kk][m0t+i]);
                    a[i]=t.x; a[i+1]=t.y; a[i+2]=t.z; a[i+3]=t.w;
                }
                #pragma unroll
                for (int j = 0; j < TN; j += 4) {
                    float4 t = *reinterpret_cast<const float4*>(&Ws[kk][n0t+j]);
                    bb[j]=t.x; bb[j+1]=t.y; bb[j+2]=t.z; bb[j+3]=t.w;
                }
                #pragma unroll
                for (int i = 0; i < TM; i++)
                    #pragma unroll
                    for (int j = 0; j < TN; j++)
                        acc[i][j] = fmaf(a[i], bb[j], acc[i][j]);
            }
            __syncthreads();
        }
    }
    #pragma unroll
    for (int j = 0; j < TN; j++) {
        int gn = n0 + n0t + j;
        float bias = (b1 ? b1[gn] : 0.f) + (b2 ? b2[gn] : 0.f);
        #pragma unroll
        for (int i = 0; i < TM; i++) {
            int gm = m0 + m0t + i;
            if (gm < M) {
                float vo = acc[i][j] + bias;
                if (relu) vo = fmaxf(vo, 0.f);
                C[(size_t)gm*ldc + gn] = vo;
            }
        }
    }
}

// ---------------- attention --------------------------------------------------
__global__ __launch_bounds__(256)
void attn_kernel(const float* __restrict__ q, const float* __restrict__ k,
                 const float* __restrict__ v, float* __restrict__ ctx)
{
    const int b = blockIdx.x, tid = threadIdx.x;
    const int lane = tid & 31, wid = tid >> 5;
    float p[S_];
    #pragma unroll
    for (int s = 0; s < S_; s++) p[s] = 0.f;
    for (int e = tid; e < H_; e += 256) {
        float qv = q[b*H_ + e];
        #pragma unroll
        for (int s = 0; s < S_; s++) p[s] = fmaf(qv, k[s*H_ + e], p[s]);
    }
    #pragma unroll
    for (int s = 0; s < S_; s++)
        #pragma unroll
        for (int off = 16; off > 0; off >>= 1)
            p[s] += __shfl_down_sync(0xffffffffu, p[s], off);
    __shared__ float sred[S_*8];
    __shared__ float wts[S_];
    if (lane == 0)
        #pragma unroll
        for (int s = 0; s < S_; s++) sred[s*8 + wid] = p[s];
    __syncthreads();
    if (tid == 0) {
        float sc[S_]; float mx = -1e30f;
        #pragma unroll
        for (int s = 0; s < S_; s++) {
            float a = 0.f;
            #pragma unroll
            for (int w = 0; w < 8; w++) a += sred[s*8 + w];
            sc[s] = a * (1.0f/32.0f);
            mx = fmaxf(mx, sc[s]);
        }
        float sum = 0.f;
        #pragma unroll
        for (int s = 0; s < S_; s++) { sc[s] = expf(sc[s]-mx); sum += sc[s]; }
        float inv = 1.f/sum;
        #pragma unroll
        for (int s = 0; s < S_; s++) wts[s] = sc[s]*inv;
    }
    __syncthreads();
    for (int j = tid; j < H_; j += 256) {
        float a = 0.f;
        #pragma unroll
        for (int s = 0; s < S_; s++) a = fmaf(wts[s], v[s*H_ + j], a);
        ctx[b*H_ + j] = a;
    }
}

// ---------------- splits ------------------------------------------------------
__global__ __launch_bounds__(256)
void split_kernel(const float* __restrict__ src, bf16* __restrict__ hi,
                  bf16* __restrict__ lo, int n)
{
    int i = blockIdx.x*blockDim.x + threadIdx.x;
    if (i < n) {
        float v = src[i];
        bf16 h = __float2bfloat16(v);
        hi[i] = h;
        lo[i] = __float2bfloat16(v - __bfloat162float(h));
    }
}

// gate-interleaving split: out row n = 4*j + g  <-  in row g*H + j   (in: [4H, K])
__global__ __launch_bounds__(256)
void split_gate_kernel(const float* __restrict__ src, bf16* __restrict__ hi,
                       bf16* __restrict__ lo, int K, int n)
{
    int i = blockIdx.x*blockDim.x + threadIdx.x;
    if (i < n) {
        int row = i / K, k = i - row * K;
        int orow = (row & 3) * H_ + (row >> 2);
        float v = src[(size_t)orow * K + k];
        bf16 h = __float2bfloat16(v);
        hi[i] = h;
        lo[i] = __float2bfloat16(v - __bfloat162float(h));
    }
}

__global__ __launch_bounds__(256)
void zero_state_kernel()
{
    int i = blockIdx.x*blockDim.x + threadIdx.x;
    if (i < B_*H_) {
        g_c0[i] = 0.f; g_c1[i] = 0.f;
        bf16 z = __float2bfloat16(0.f);
        g_h0h[0][i] = z; g_h0l[0][i] = z; g_h1h[0][i] = z; g_h1l[0][i] = z;
        g_h0h[1][i] = z; g_h0l[1][i] = z; g_h1h[1][i] = z; g_h1l[1][i] = z;
    }
    if (i < 4*32) g_cnt[i] = 0;
    if (i == 0) { g_cnt2 = 0; g_gen = 0; }
}

// ---------------- host helpers -------------------------------------------------
static inline void gemm_small(const float* A1,int lda1,const float* W1,int ldw1,int K1,
                              const float* A2,int lda2,const float* W2,int ldw2,int K2,
                              const float* b1,const float* b2,
                              float* C,int ldc,int M,int N,int relu)
{
    dim3 grid(N/32, (M + 63)/64);
    gemm2_kernel<64,32,16,4,4,128><<<grid,128>>>(A1,lda1,W1,ldw1,K1,
                                                 A2,lda2,W2,ldw2,K2,
                                                 b1,b2,C,ldc,M,N,relu);
}

extern "C" void kernel_launch(void* const* d_in, const int* in_sizes, int n_in,
                              void* d_out, int out_size)
{
    (void)in_sizes; (void)n_in;
    const float* cs   = (const float*)d_in[0];
    const float* mem  = (const float*)d_in[2];
    const float* qW   = (const float*)d_in[3];
    const float* qb   = (const float*)d_in[4];
    const float* kW   = (const float*)d_in[5];
    const float* kb   = (const float*)d_in[6];
    const float* vW   = (const float*)d_in[7];
    const float* vb   = (const float*)d_in[8];
    const float* moW  = (const float*)d_in[9];
    const float* mob  = (const float*)d_in[10];
    const float* pgW1 = (const float*)d_in[11];
    const float* pgb1 = (const float*)d_in[12];
    const float* pgW2 = (const float*)d_in[13];
    const float* pgb2 = (const float*)d_in[14];
    const float* wih0 = (const float*)d_in[15];
    const float* whh0 = (const float*)d_in[16];
    const float* bih0 = (const float*)d_in[17];
    const float* bhh0 = (const float*)d_in[18];
    const float* wih1 = (const float*)d_in[19];
    const float* whh1 = (const float*)d_in[20];
    const float* bih1 = (const float*)d_in[21];
    const float* bhh1 = (const float*)d_in[22];
    const float* opW1 = (const float*)d_in[23];
    const float* opb1 = (const float*)d_in[24];
    const float* opW2 = (const float*)d_in[25];
    const float* opb2 = (const float*)d_in[26];

    float* out = (float*)d_out;

    cudaFuncSetAttribute(rollout_kernel, cudaFuncAttributeMaxDynamicSharedMemorySize, P_SMEM);

    // scratch addresses
    float *q,*km,*vm,*ctx,*cxt,*pgh,*prior_s;
    cudaGetSymbolAddress((void**)&q, g_q);
    cudaGetSymbolAddress((void**)&km, g_kmem);
    cudaGetSymbolAddress((void**)&vm, g_vmem);
    cudaGetSymbolAddress((void**)&ctx, g_ctx);
    cudaGetSymbolAddress((void**)&cxt, g_context);
    cudaGetSymbolAddress((void**)&pgh, g_pgh);
    cudaGetSymbolAddress((void**)&prior_s, g_prior);

    bf16 *xh,*xl;
    bf16 *wih0h,*wih0l,*whh0h,*whh0l,*wih1h,*wih1l,*whh1h,*whh1l,*oW1h,*oW1l,*oW2h,*oW2l;
    cudaGetSymbolAddress((void**)&xh, g_xh);   cudaGetSymbolAddress((void**)&xl, g_xl);
    cudaGetSymbolAddress((void**)&wih0h, g_wih0h); cudaGetSymbolAddress((void**)&wih0l, g_wih0l);
    cudaGetSymbolAddress((void**)&whh0h, g_whh0h); cudaGetSymbolAddress((void**)&whh0l, g_whh0l);
    cudaGetSymbolAddress((void**)&wih1h, g_wih1h); cudaGetSymbolAddress((void**)&wih1l, g_wih1l);
    cudaGetSymbolAddress((void**)&whh1h, g_whh1h); cudaGetSymbolAddress((void**)&whh1l, g_whh1l);
    cudaGetSymbolAddress((void**)&oW1h, g_opW1h);  cudaGetSymbolAddress((void**)&oW1l, g_opW1l);
    cudaGetSymbolAddress((void**)&oW2h, g_opW2h);  cudaGetSymbolAddress((void**)&oW2l, g_opW2l);

    bool has_prior_region = (out_size >= PRED_ELEMS + B_*L_);
    float* priorbuf = has_prior_region ? (out + PRED_ELEMS) : prior_s;

    // ---- state init + weight conversion (gate weights permuted to 4j+g order)
    zero_state_kernel<<<(B_*H_ + 255)/256, 256>>>();
    split_gate_kernel<<<(4*H_*L_ + 255)/256, 256>>>(wih0, wih0h, wih0l, L_, 4*H_*L_);
    split_gate_kernel<<<(4*H_*H_ + 255)/256, 256>>>(whh0, whh0h, whh0l, H_, 4*H_*H_);
    split_gate_kernel<<<(4*H_*H_ + 255)/256, 256>>>(wih1, wih1h, wih1l, H_, 4*H_*H_);
    split_gate_kernel<<<(4*H_*H_ + 255)/256, 256>>>(whh1, whh1h, whh1l, H_, 4*H_*H_);
    split_kernel<<<(H_*H_ + 255)/256, 256>>>(opW1, oW1h, oW1l, H_*H_);
    split_kernel<<<(L_*H_ + 255)/256, 256>>>(opW2, oW2h, oW2l, L_*H_);

    // ---- prologue (fp32) ----
    gemm_small(cs, L_, qW, L_, L_,  nullptr,0,nullptr,0,0, qb,nullptr, q,  H_, B_, H_, 0);
    gemm_small(mem,H_, kW, H_, H_,  nullptr,0,nullptr,0,0, kb,nullptr, km, H_, S_, H_, 0);
    gemm_small(mem,H_, vW, H_, H_,  nullptr,0,nullptr,0,0, vb,nullptr, vm, H_, S_, H_, 0);
    attn_kernel<<<B_, 256>>>(q, km, vm, ctx);
    gemm_small(ctx,H_, moW,H_, H_,  nullptr,0,nullptr,0,0, mob,nullptr, cxt, L_, B_, L_, 0);
    gemm_small(cs, L_, pgW1,      2*L_, L_,
               cxt,L_, pgW1 + L_, 2*L_, L_,
               pgb1, nullptr, pgh, H_, B_, H_, 1);
    gemm_small(pgh,H_, pgW2,H_, H_, nullptr,0,nullptr,0,0, pgb2,nullptr,
               priorbuf, L_, B_, L_, 0);
    split_kernel<<<(B_*L_ + 255)/256, 256>>>(priorbuf, xh, xl, B_*L_);

    // ---- persistent rollout: ONE kernel, 4 phases/step, 128 CTAs x 256 thr --
    rollout_kernel<<<128, 256, P_SMEM>>>(bih0, bhh0, bih1, bhh1, opb1, opb2, out);
}

// round 13
// speedup vs baseline: 1.1041x; 1.1041x over previous
#include <cuda_runtime.h>
#include <cuda_bf16.h>
#include <math.h>
#include <stdint.h>

#define B_ 256
#define L_ 512
#define H_ 1024
#define S_ 16
#define HOR_ 64
#define PRED_ELEMS (B_*HOR_*L_)

typedef __nv_bfloat16 bf16;

// ---------------- fp32 scratch ----------------------------------------------
__device__ float g_q[B_*H_];
__device__ float g_kmem[S_*H_];
__device__ float g_vmem[S_*H_];
__device__ float g_ctx[B_*H_];
__device__ float g_context[B_*L_];
__device__ float g_pgh[B_*H_];
__device__ float g_prior[B_*L_];
__device__ float g_c0[B_*H_];
__device__ float g_c1[B_*H_];

// ---------------- bf16 split scratch ----------------------------------------
__device__ __align__(16) bf16 g_xh[B_*L_],  g_xl[B_*L_];
__device__ __align__(16) bf16 g_h0h[2][B_*H_], g_h0l[2][B_*H_];
__device__ __align__(16) bf16 g_h1h[2][B_*H_], g_h1l[2][B_*H_];
__device__ __align__(16) bf16 g_th[B_*H_],  g_tl[B_*H_];
__device__ __align__(16) bf16 g_wih0h[4*H_*L_], g_wih0l[4*H_*L_];
__device__ __align__(16) bf16 g_whh0h[4*H_*H_], g_whh0l[4*H_*H_];
__device__ __align__(16) bf16 g_wih1h[4*H_*H_], g_wih1l[4*H_*H_];
__device__ __align__(16) bf16 g_whh1h[4*H_*H_], g_whh1l[4*H_*H_];
__device__ __align__(16) bf16 g_opW1h[H_*H_],   g_opW1l[H_*H_];
__device__ __align__(16) bf16 g_opW2h[L_*H_],   g_opW2l[L_*H_];

// ---------------- hierarchical grid barrier (256 CTAs: 8 x 32) ---------------
__device__ unsigned g_cnt[8*32];
__device__ unsigned g_cnt2 = 0;
__device__ unsigned g_gen  = 0;

// ---------------- low-level helpers ------------------------------------------
__device__ __forceinline__ uint32_t smem_u32(const void* p) {
    uint32_t a;
    asm("{ .reg .u64 t; cvta.to.shared.u64 t, %1; cvt.u32.u64 %0, t; }" : "=r"(a) : "l"(p));
    return a;
}

#define CP_ASYNC16(d, s) \
    asm volatile("cp.async.cg.shared.global [%0], [%1], 16;" :: "r"(d), "l"(s))
#define CP_COMMIT()  asm volatile("cp.async.commit_group;" ::: "memory")

__device__ __forceinline__ void ldm_x4(uint32_t* r, uint32_t addr) {
    asm volatile("ldmatrix.sync.aligned.m8n8.x4.shared.b16 {%0,%1,%2,%3}, [%4];"
                 : "=r"(r[0]), "=r"(r[1]), "=r"(r[2]), "=r"(r[3]) : "r"(addr));
}

__device__ __forceinline__ void mma16816(float* d, const uint32_t* a, const uint32_t* b) {
    asm volatile(
        "mma.sync.aligned.m16n8k16.row.col.f32.bf16.bf16.f32 "
        "{%0,%1,%2,%3}, {%4,%5,%6,%7}, {%8,%9}, {%0,%1,%2,%3};"
        : "+f"(d[0]), "+f"(d[1]), "+f"(d[2]), "+f"(d[3])
        : "r"(a[0]), "r"(a[1]), "r"(a[2]), "r"(a[3]), "r"(b[0]), "r"(b[1]));
}

__device__ __forceinline__ void grid_sync() {
    __syncthreads();
    if (threadIdx.x == 0) {
        volatile unsigned* genp = (volatile unsigned*)&g_gen;
        const unsigned gen = *genp;
        __threadfence();
        unsigned old = atomicAdd(&g_cnt[(blockIdx.x & 7) * 32], 1u);
        bool flipped = false;
        if (old == 31u) {
            unsigned old2 = atomicAdd(&g_cnt2, 1u);
            if (old2 == 7u) {
                #pragma unroll
                for (int i = 0; i < 8; i++) g_cnt[i * 32] = 0u;
                g_cnt2 = 0u;
                __threadfence();
                *genp = gen + 1u;
                flipped = true;
            }
        }
        if (!flipped) {
            while (*genp == gen) { }
        }
        __threadfence();
    }
    __syncthreads();
}

// ---------------- device GEMM core (dual source) -----------------------------
// NTHR threads load; NWM x NWN compute warps do the MMA (others idle but sync).
#define PSTRIDE 40
#define P_SMEM (3 * (2*(64+64)) * PSTRIDE * 2)   // 61440

template<int BM, int BN, int NWM, int NWN, int NTHR>
__device__ __forceinline__ void gemm_dual(
    uint32_t sb, int tid,
    const bf16* __restrict__ Ah1, const bf16* __restrict__ Al1, int lda1,
    const bf16* __restrict__ Wh1, const bf16* __restrict__ Wl1, int ldw1, int nc1,
    const bf16* __restrict__ Ah2, const bf16* __restrict__ Al2, int lda2,
    const bf16* __restrict__ Wh2, const bf16* __restrict__ Wl2, int ldw2, int nc2,
    float (&acc)[(BM/NWM)/16][2*((BN/NWN)/16)][4])
{
    constexpr int CW  = NWM * NWN;          // compute warps
    constexpr int WM  = BM / NWM;
    constexpr int WN  = BN / NWN;
    constexpr int MI  = WM / 16;
    constexpr int NJ  = WN / 16;
    constexpr int AHo = 0;
    constexpr int ALo = BM * PSTRIDE;
    constexpr int WHo = 2 * BM * PSTRIDE;
    constexpr int WLo = (2 * BM + BN) * PSTRIDE;
    constexpr int STAGE_B = 2 * (BM + BN) * PSTRIDE * 2;

    const int lane = tid & 31, wid = tid >> 5;
    const int warp_m = wid / NWN, warp_n = wid % NWN;
    const bool comp = (wid < CW);
    const int nc = nc1 + nc2;

    auto do_load = [&](int c) {
        const int src = (c < nc1) ? 0 : 1;
        const int k0  = ((src == 0) ? c : (c - nc1)) << 5;
        const bf16* Ah = src ? Ah2 : Ah1;
        const bf16* Al = src ? Al2 : Al1;
        const bf16* Wh = src ? Wh2 : Wh1;
        const bf16* Wl = src ? Wl2 : Wl1;
        const int lda = src ? lda2 : lda1;
        const int ldw = src ? ldw2 : ldw1;
        const uint32_t st = sb + (uint32_t)(c % 3) * STAGE_B;

        constexpr int T16 = 2 * (BM + BN) * 4;
        #pragma unroll
        for (int it = 0; it < T16 / NTHR; it++) {
            int idx = tid + it * NTHR;
            int row = idx >> 2, ch = idx & 3;
            const bf16* g; int soff;
            if (row < BM)             {               g = Ah + (size_t)row * lda; soff = AHo + row * PSTRIDE; }
            else if (row < 2*BM)      { int r = row - BM;   g = Al + (size_t)r * lda; soff = ALo + r * PSTRIDE; }
            else if (row < 2*BM + BN) { int r = row - 2*BM; g = Wh + (size_t)r * ldw; soff = WHo + r * PSTRIDE; }
            else                      { int r = row - 2*BM - BN; g = Wl + (size_t)r * ldw; soff = WLo + r * PSTRIDE; }
            CP_ASYNC16(st + (uint32_t)(soff + ch * 8) * 2, g + k0 + ch * 8);
        }
        CP_COMMIT();
    };

    do_load(0);
    if (nc > 1) do_load(1);

    const int a_row = warp_m * WM + (lane & 15);
    const int a_kof = (lane >> 4) << 3;
    const int b_row = warp_n * WN + ((lane >> 4) << 3) + (lane & 7);
    const int b_kof = ((lane >> 3) & 1) << 3;

    for (int c = 0; c < nc; c++) {
        if (c + 1 < nc) asm volatile("cp.async.wait_group 1;" ::: "memory");
        else            asm volatile("cp.async.wait_group 0;" ::: "memory");
        __syncthreads();

        if (c + 2 < nc) do_load(c + 2);

        const uint32_t st = sb + (uint32_t)(c % 3) * STAGE_B;

        if (comp) {
            #pragma unroll
            for (int k16 = 0; k16 < 2; k16++) {
                const int kk = k16 * 16;
                uint32_t ah[MI][4], al[MI][4], bh[NJ][4], bl[NJ][4];
                #pragma unroll
                for (int mi = 0; mi < MI; mi++) {
                    ldm_x4(ah[mi], st + (uint32_t)((AHo + (a_row + mi*16) * PSTRIDE + kk + a_kof) * 2));
                    ldm_x4(al[mi], st + (uint32_t)((ALo + (a_row + mi*16) * PSTRIDE + kk + a_kof) * 2));
                }
                #pragma unroll
                for (int g = 0; g < NJ; g++) {
                    ldm_x4(bh[g], st + (uint32_t)((WHo + (b_row + g*16) * PSTRIDE + kk + b_kof) * 2));
                    ldm_x4(bl[g], st + (uint32_t)((WLo + (b_row + g*16) * PSTRIDE + kk + b_kof) * 2));
                }
                #pragma unroll
                for (int mi = 0; mi < MI; mi++)
                    #pragma unroll
                    for (int nj = 0; nj < 2*NJ; nj++) {
                        const int g = nj >> 1, o = (nj & 1) * 2;
                        mma16816(acc[mi][nj], ah[mi], &bh[g][o]);
                        mma16816(acc[mi][nj], al[mi], &bh[g][o]);
                        mma16816(acc[mi][nj], ah[mi], &bl[g][o]);
                    }
            }
        }
    }
    __syncthreads();
}

template<int MI, int NJ2>
__device__ __forceinline__ void zero_acc(float (&acc)[MI][NJ2][4]) {
    #pragma unroll
    for (int i = 0; i < MI; i++)
        #pragma unroll
        for (int j = 0; j < NJ2; j++)
            #pragma unroll
            for (int r = 0; r < 4; r++) acc[i][j][r] = 0.f;
}

// fused LSTM cell epilogue; generic warp grid; col n = 4*j + gate
template<int MI, int NJ, int NWN>
__device__ __forceinline__ void cell_epi(
    float (&acc)[MI][2*NJ][4], int tid, int m0, int n0,
    const float* __restrict__ b1, const float* __restrict__ b2,
    const float* __restrict__ cin, float* __restrict__ cout,
    bf16* __restrict__ Oh, bf16* __restrict__ Ol)
{
    const int lane = tid & 31, wid = tid >> 5;
    const int warp_m = wid / NWN, warp_n = wid % NWN;
    const int m_base = m0 + warp_m * (MI * 16);
    const int n_base = n0 + warp_n * (NJ * 16);
    #pragma unroll
    for (int mi = 0; mi < MI; mi++) {
        #pragma unroll
        for (int nj = 0; nj < 2*NJ; nj++) {
            const int c0 = n_base + nj * 8 + (lane & 3) * 2;
            const int bi0 = (c0 & 3) * H_ + (c0 >> 2);
            const int bi1 = ((c0 + 1) & 3) * H_ + ((c0 + 1) >> 2);
            const float bias0 = b1[bi0] + b2[bi0];
            const float bias1 = b1[bi1] + b2[bi1];
            #pragma unroll
            for (int half = 0; half < 2; half++) {
                const int row = m_base + mi * 16 + (lane >> 2) + half * 8;
                float v0 = acc[mi][nj][half*2 + 0] + bias0;
                float v1 = acc[mi][nj][half*2 + 1] + bias1;
                float p0 = __shfl_xor_sync(0xffffffffu, v0, 1);
                float p1 = __shfl_xor_sync(0xffffffffu, v1, 1);
                if ((lane & 1) == 0) {
                    const int j   = c0 >> 2;
                    const int idx = row * H_ + j;
                    float ig = 1.f / (1.f + expf(-v0));
                    float fg = 1.f / (1.f + expf(-v1));
                    float gg = tanhf(p0);
                    float og = 1.f / (1.f + expf(-p1));
                    float cv = fg * cin[idx] + ig * gg;
                    float hv = og * tanhf(cv);
                    cout[idx] = cv;
                    bf16 hb = __float2bfloat16(hv);
                    Oh[idx] = hb;
                    Ol[idx] = __float2bfloat16(hv - __bfloat162float(hb));
                }
            }
        }
    }
}

// standard epilogue: bias (+relu), optional fp32 C, optional bf16 hi/lo split
template<int MI, int NJ, int NWN>
__device__ __forceinline__ void std_epi(
    float (&acc)[MI][2*NJ][4], int tid, int m0, int n0,
    const float* __restrict__ b,
    float* __restrict__ C, int ldc,
    bf16* __restrict__ Oh, bf16* __restrict__ Ol, int ldo, int relu)
{
    const int lane = tid & 31, wid = tid >> 5;
    const int warp_m = wid / NWN, warp_n = wid % NWN;
    const int m_base = m0 + warp_m * (MI * 16);
    const int n_base = n0 + warp_n * (NJ * 16);
    #pragma unroll
    for (int mi = 0; mi < MI; mi++) {
        #pragma unroll
        for (int nj = 0; nj < 2*NJ; nj++) {
            const int col = n_base + nj * 8 + (lane & 3) * 2;
            const float bias0 = b[col];
            const float bias1 = b[col + 1];
            #pragma unroll
            for (int half = 0; half < 2; half++) {
                const int row = m_base + mi * 16 + (lane >> 2) + half * 8;
                float v0 = acc[mi][nj][half*2 + 0] + bias0;
                float v1 = acc[mi][nj][half*2 + 1] + bias1;
                if (relu) { v0 = fmaxf(v0, 0.f); v1 = fmaxf(v1, 0.f); }
                if (C)
                    *reinterpret_cast<float2*>(C + (size_t)row * ldc + col) =
                        make_float2(v0, v1);
                if (Oh) {
                    bf16 h0 = __float2bfloat16(v0);
                    bf16 h1 = __float2bfloat16(v1);
                    bf16 l0 = __float2bfloat16(v0 - __bfloat162float(h0));
                    bf16 l1 = __float2bfloat16(v1 - __bfloat162float(h1));
                    bf16 hp[2] = {h0, h1}, lp[2] = {l0, l1};
                    *reinterpret_cast<uint32_t*>(Oh + (size_t)row * ldo + col) =
                        *reinterpret_cast<uint32_t*>(hp);
                    *reinterpret_cast<uint32_t*>(Ol + (size_t)row * ldo + col) =
                        *reinterpret_cast<uint32_t*>(lp);
                }
            }
        }
    }
}

// ---------------- persistent rollout kernel ----------------------------------
// 256 CTAs x 256 threads; 2 CTAs/SM -> 4 warps/SMSP.
__global__ void __launch_bounds__(256, 2)
rollout_kernel(const float* __restrict__ bih0, const float* __restrict__ bhh0,
               const float* __restrict__ bih1, const float* __restrict__ bhh1,
               const float* __restrict__ opb1, const float* __restrict__ opb2,
               float* __restrict__ out)
{
    extern __shared__ __align__(16) char smem[];
    const uint32_t sb = smem_u32(smem);
    const int tid = threadIdx.x;
    const int cta = blockIdx.x;

    // gates mapping: 4 m-tiles x 64 n-tiles (tile 64x64, 8 compute warps 2x4)
    const int gm0 = (cta & 3) * 64;
    const int gn0 = (cta >> 2) * 64;
    // op mapping: 8 m x 32 n (op1, tile 32x32) / 8 m x 16 n (op2)
    const int o1m = (cta & 7) * 32, o1n = (cta >> 3) * 32;
    const int o2m = (cta & 7) * 32, o2n = (cta >> 3) * 32;

    for (int s = 0; s < HOR_; s++) {
        const int p = s & 1, pn = p ^ 1;

        // ---- phase 1: gates0 (x@wih0 + h0@whh0) + cell -> h0[pn], c0 ----
        {
            float acc[2][2][4];
            zero_acc(acc);
            gemm_dual<64,64,2,4,256>(sb, tid,
                g_xh + (size_t)gm0*L_, g_xl + (size_t)gm0*L_, L_,
                g_wih0h + (size_t)gn0*L_, g_wih0l + (size_t)gn0*L_, L_, L_/32,
                g_h0h[p] + (size_t)gm0*H_, g_h0l[p] + (size_t)gm0*H_, H_,
                g_whh0h + (size_t)gn0*H_, g_whh0l + (size_t)gn0*H_, H_, H_/32,
                acc);
            cell_epi<2,1,4>(acc, tid, gm0, gn0, bih0, bhh0, g_c0, g_c0,
                            g_h0h[pn], g_h0l[pn]);
        }
        grid_sync();

        // ---- phase 2: gates1 (h0@wih1 + h1@whh1) + cell -> h1[pn], c1 ----
        {
            float acc[2][2][4];
            zero_acc(acc);
            gemm_dual<64,64,2,4,256>(sb, tid,
                g_h0h[pn] + (size_t)gm0*H_, g_h0l[pn] + (size_t)gm0*H_, H_,
                g_wih1h + (size_t)gn0*H_, g_wih1l + (size_t)gn0*H_, H_, H_/32,
                g_h1h[p] + (size_t)gm0*H_, g_h1l[p] + (size_t)gm0*H_, H_,
                g_whh1h + (size_t)gn0*H_, g_whh1l + (size_t)gn0*H_, H_, H_/32,
                acc);
            cell_epi<2,1,4>(acc, tid, gm0, gn0, bih1, bhh1, g_c1, g_c1,
                            g_h1h[pn], g_h1l[pn]);
        }
        grid_sync();

        // ---- phase 3: op1 = relu(h1 @ opW1^T + b1) -> th/tl (32x32, 256 CTAs)
        {
            float acc[1][2][4];
            zero_acc(acc);
            gemm_dual<32,32,2,2,256>(sb, tid,
                g_h1h[pn] + (size_t)o1m*H_, g_h1l[pn] + (size_t)o1m*H_, H_,
                g_opW1h + (size_t)o1n*H_, g_opW1l + (size_t)o1n*H_, H_, H_/32,
                nullptr, nullptr, 0, nullptr, nullptr, 0, 0,
                acc);
            if ((tid >> 5) < 4)
                std_epi<1,1,2>(acc, tid, o1m, o1n, opb1, nullptr, 0, g_th, g_tl, H_, 1);
        }
        grid_sync();

        // ---- phase 4: op2 = t @ opW2^T + b2 -> out + x split (32x32, 128 CTAs)
        if (cta < 128) {
            float acc[1][2][4];
            zero_acc(acc);
            gemm_dual<32,32,2,2,256>(sb, tid,
                g_th + (size_t)o2m*H_, g_tl + (size_t)o2m*H_, H_,
                g_opW2h + (size_t)o2n*H_, g_opW2l + (size_t)o2n*H_, H_, H_/32,
                nullptr, nullptr, 0, nullptr, nullptr, 0, 0,
                acc);
            if ((tid >> 5) < 4)
                std_epi<1,1,2>(acc, tid, o2m, o2n, opb2,
                               out + (size_t)s * L_, HOR_*L_, g_xh, g_xl, L_, 0);
        }
        grid_sync();
    }
}

// ---------------- fp32 GEMM (prologue only) ---------------------------------
template<int BM,int BN,int BK,int TM,int TN,int NT>
__global__ __launch_bounds__(NT)
void gemm2_kernel(const float* __restrict__ A1, int lda1,
                  const float* __restrict__ W1, int ldw1, int K1,
                  const float* __restrict__ A2, int lda2,
                  const float* __restrict__ W2, int ldw2, int K2,
                  const float* __restrict__ b1, const float* __restrict__ b2,
                  float* __restrict__ C, int ldc, int M, int N, int relu)
{
    __shared__ __align__(16) float As[BK][BM+4];
    __shared__ __align__(16) float Ws[BK][BN+4];
    const int tid = threadIdx.x;
    const int m0  = blockIdx.y * BM;
    const int n0  = blockIdx.x * BN;
    const int m0t = (tid / (BN/TN)) * TM;
    const int n0t = (tid % (BN/TN)) * TN;
    float acc[TM][TN];
    #pragma unroll
    for (int i = 0; i < TM; i++)
        #pragma unroll
        for (int j = 0; j < TN; j++) acc[i][j] = 0.f;
    for (int src = 0; src < 2; src++) {
        const float* A = src ? A2 : A1;
        if (A == nullptr) break;
        const float* W = src ? W2 : W1;
        const int lda = src ? lda2 : lda1;
        const int ldw = src ? ldw2 : ldw1;
        const int K   = src ? K2   : K1;
        for (int k0 = 0; k0 < K; k0 += BK) {
            constexpr int A4 = BM*BK/4;
            #pragma unroll
            for (int it = 0; it < A4/NT; it++) {
                int i4 = tid + NT*it;
                int row = i4 / (BK/4), cv = i4 % (BK/4);
                float4 val = make_float4(0,0,0,0);
                int gr = m0 + row;
                if (gr < M) val = *reinterpret_cast<const float4*>(A + (size_t)gr*lda + k0 + cv*4);
                As[cv*4+0][row]=val.x; As[cv*4+1][row]=val.y;
                As[cv*4+2][row]=val.z; As[cv*4+3][row]=val.w;
            }
            constexpr int W4 = BN*BK/4;
            #pragma unroll
            for (int it = 0; it < W4/NT; it++) {
                int i4 = tid + NT*it;
                int row = i4 / (BK/4), cv = i4 % (BK/4);
                float4 val = *reinterpret_cast<const float4*>(W + (size_t)(n0+row)*ldw + k0 + cv*4);
                Ws[cv*4+0][row]=val.x; Ws[cv*4+1][row]=val.y;
                Ws[cv*4+2][row]=val.z; Ws[cv*4+3][row]=val.w;
            }
            __syncthreads();
            #pragma unroll
            for (int kk = 0; kk < BK; kk++) {
                float a[TM], bb[TN];
                #pragma unroll
                for (int i = 0; i < TM; i += 4) {
                    float4 t = *reinterpret_cast<const float4*>(&As[kk][m0t+i]);
                    a[i]=t.x; a[i+1]=t.y; a[i+2]=t.z; a[i+3]=t.w;
                }
                #pragma unroll
                for (int j = 0; j < TN; j += 4) {
                    float4 t = *reinterpret_cast<const float4*>(&Ws[kk][n0t+j]);
                    bb[j]=t.x; bb[j+1]=t.y; bb[j+2]=t.z; bb[j+3]=t.w;
                }
                #pragma unroll
                for (int i = 0; i < TM; i++)
                    #pragma unroll
                    for (int j = 0; j < TN; j++)
                        acc[i][j] = fmaf(a[i], bb[j], acc[i][j]);
            }
            __syncthreads();
        }
    }
    #pragma unroll
    for (int j = 0; j < TN; j++) {
        int gn = n0 + n0t + j;
        float bias = (b1 ? b1[gn] : 0.f) + (b2 ? b2[gn] : 0.f);
        #pragma unroll
        for (int i = 0; i < TM; i++) {
            int gm = m0 + m0t + i;
            if (gm < M) {
                float vo = acc[i][j] + bias;
                if (relu) vo = fmaxf(vo, 0.f);
                C[(size_t)gm*ldc + gn] = vo;
            }
        }
    }
}

// ---------------- attention --------------------------------------------------
__global__ __launch_bounds__(256)
void attn_kernel(const float* __restrict__ q, const float* __restrict__ k,
                 const float* __restrict__ v, float* __restrict__ ctx)
{
    const int b = blockIdx.x, tid = threadIdx.x;
    const int lane = tid & 31, wid = tid >> 5;
    float p[S_];
    #pragma unroll
    for (int s = 0; s < S_; s++) p[s] = 0.f;
    for (int e = tid; e < H_; e += 256) {
        float qv = q[b*H_ + e];
        #pragma unroll
        for (int s = 0; s < S_; s++) p[s] = fmaf(qv, k[s*H_ + e], p[s]);
    }
    #pragma unroll
    for (int s = 0; s < S_; s++)
        #pragma unroll
        for (int off = 16; off > 0; off >>= 1)
            p[s] += __shfl_down_sync(0xffffffffu, p[s], off);
    __shared__ float sred[S_*8];
    __shared__ float wts[S_];
    if (lane == 0)
        #pragma unroll
        for (int s = 0; s < S_; s++) sred[s*8 + wid] = p[s];
    __syncthreads();
    if (tid == 0) {
        float sc[S_]; float mx = -1e30f;
        #pragma unroll
        for (int s = 0; s < S_; s++) {
            float a = 0.f;
            #pragma unroll
            for (int w = 0; w < 8; w++) a += sred[s*8 + w];
            sc[s] = a * (1.0f/32.0f);
            mx = fmaxf(mx, sc[s]);
        }
        float sum = 0.f;
        #pragma unroll
        for (int s = 0; s < S_; s++) { sc[s] = expf(sc[s]-mx); sum += sc[s]; }
        float inv = 1.f/sum;
        #pragma unroll
        for (int s = 0; s < S_; s++) wts[s] = sc[s]*inv;
    }
    __syncthreads();
    for (int j = tid; j < H_; j += 256) {
        float a = 0.f;
        #pragma unroll
        for (int s = 0; s < S_; s++) a = fmaf(wts[s], v[s*H_ + j], a);
        ctx[b*H_ + j] = a;
    }
}

// ---------------- splits ------------------------------------------------------
__global__ __launch_bounds__(256)
void split_kernel(const float* __restrict__ src, bf16* __restrict__ hi,
                  bf16* __restrict__ lo, int n)
{
    int i = blockIdx.x*blockDim.x + threadIdx.x;
    if (i < n) {
        float v = src[i];
        bf16 h = __float2bfloat16(v);
        hi[i] = h;
        lo[i] = __float2bfloat16(v - __bfloat162float(h));
    }
}

// gate-interleaving split: out row n = 4*j + g  <-  in row g*H + j   (in: [4H, K])
__global__ __launch_bounds__(256)
void split_gate_kernel(const float* __restrict__ src, bf16* __restrict__ hi,
                       bf16* __restrict__ lo, int K, int n)
{
    int i = blockIdx.x*blockDim.x + threadIdx.x;
    if (i < n) {
        int row = i / K, k = i - row * K;
        int orow = (row & 3) * H_ + (row >> 2);
        float v = src[(size_t)orow * K + k];
        bf16 h = __float2bfloat16(v);
        hi[i] = h;
        lo[i] = __float2bfloat16(v - __bfloat162float(h));
    }
}

__global__ __launch_bounds__(256)
void zero_state_kernel()
{
    int i = blockIdx.x*blockDim.x + threadIdx.x;
    if (i < B_*H_) {
        g_c0[i] = 0.f; g_c1[i] = 0.f;
        bf16 z = __float2bfloat16(0.f);
        g_h0h[0][i] = z; g_h0l[0][i] = z; g_h1h[0][i] = z; g_h1l[0][i] = z;
        g_h0h[1][i] = z; g_h0l[1][i] = z; g_h1h[1][i] = z; g_h1l[1][i] = z;
    }
    if (i < 8*32) g_cnt[i] = 0;
    if (i == 0) { g_cnt2 = 0; g_gen = 0; }
}

// ---------------- host helpers -------------------------------------------------
static inline void gemm_small(const float* A1,int lda1,const float* W1,int ldw1,int K1,
                              const float* A2,int lda2,const float* W2,int ldw2,int K2,
                              const float* b1,const float* b2,
                              float* C,int ldc,int M,int N,int relu)
{
    dim3 grid(N/32, (M + 63)/64);
    gemm2_kernel<64,32,16,4,4,128><<<grid,128>>>(A1,lda1,W1,ldw1,K1,
                                                 A2,lda2,W2,ldw2,K2,
                                                 b1,b2,C,ldc,M,N,relu);
}

extern "C" void kernel_launch(void* const* d_in, const int* in_sizes, int n_in,
                              void* d_out, int out_size)
{
    (void)in_sizes; (void)n_in;
    const float* cs   = (const float*)d_in[0];
    const float* mem  = (const float*)d_in[2];
    const float* qW   = (const float*)d_in[3];
    const float* qb   = (const float*)d_in[4];
    const float* kW   = (const float*)d_in[5];
    const float* kb   = (const float*)d_in[6];
    const float* vW   = (const float*)d_in[7];
    const float* vb   = (const float*)d_in[8];
    const float* moW  = (const float*)d_in[9];
    const float* mob  = (const float*)d_in[10];
    const float* pgW1 = (const float*)d_in[11];
    const float* pgb1 = (const float*)d_in[12];
    const float* pgW2 = (const float*)d_in[13];
    const float* pgb2 = (const float*)d_in[14];
    const float* wih0 = (const float*)d_in[15];
    const float* whh0 = (const float*)d_in[16];
    const float* bih0 = (const float*)d_in[17];
    const float* bhh0 = (const float*)d_in[18];
    const float* wih1 = (const float*)d_in[19];
    const float* whh1 = (const float*)d_in[20];
    const float* bih1 = (const float*)d_in[21];
    const float* bhh1 = (const float*)d_in[22];
    const float* opW1 = (const float*)d_in[23];
    const float* opb1 = (const float*)d_in[24];
    const float* opW2 = (const float*)d_in[25];
    const float* opb2 = (const float*)d_in[26];

    float* out = (float*)d_out;

    cudaFuncSetAttribute(rollout_kernel, cudaFuncAttributeMaxDynamicSharedMemorySize, P_SMEM);

    // scratch addresses
    float *q,*km,*vm,*ctx,*cxt,*pgh,*prior_s;
    cudaGetSymbolAddress((void**)&q, g_q);
    cudaGetSymbolAddress((void**)&km, g_kmem);
    cudaGetSymbolAddress((void**)&vm, g_vmem);
    cudaGetSymbolAddress((void**)&ctx, g_ctx);
    cudaGetSymbolAddress((void**)&cxt, g_context);
    cudaGetSymbolAddress((void**)&pgh, g_pgh);
    cudaGetSymbolAddress((void**)&prior_s, g_prior);

    bf16 *xh,*xl;
    bf16 *wih0h,*wih0l,*whh0h,*whh0l,*wih1h,*wih1l,*whh1h,*whh1l,*oW1h,*oW1l,*oW2h,*oW2l;
    cudaGetSymbolAddress((void**)&xh, g_xh);   cudaGetSymbolAddress((void**)&xl, g_xl);
    cudaGetSymbolAddress((void**)&wih0h, g_wih0h); cudaGetSymbolAddress((void**)&wih0l, g_wih0l);
    cudaGetSymbolAddress((void**)&whh0h, g_whh0h); cudaGetSymbolAddress((void**)&whh0l, g_whh0l);
    cudaGetSymbolAddress((void**)&wih1h, g_wih1h); cudaGetSymbolAddress((void**)&wih1l, g_wih1l);
    cudaGetSymbolAddress((void**)&whh1h, g_whh1h); cudaGetSymbolAddress((void**)&whh1l, g_whh1l);
    cudaGetSymbolAddress((void**)&oW1h, g_opW1h);  cudaGetSymbolAddress((void**)&oW1l, g_opW1l);
    cudaGetSymbolAddress((void**)&oW2h, g_opW2h);  cudaGetSymbolAddress((void**)&oW2l, g_opW2l);

    bool has_prior_region = (out_size >= PRED_ELEMS + B_*L_);
    float* priorbuf = has_prior_region ? (out + PRED_ELEMS) : prior_s;

    // ---- state init + weight conversion (gate weights permuted to 4j+g order)
    zero_state_kernel<<<(B_*H_ + 255)/256, 256>>>();
    split_gate_kernel<<<(4*H_*L_ + 255)/256, 256>>>(wih0, wih0h, wih0l, L_, 4*H_*L_);
    split_gate_kernel<<<(4*H_*H_ + 255)/256, 256>>>(whh0, whh0h, whh0l, H_, 4*H_*H_);
    split_gate_kernel<<<(4*H_*H_ + 255)/256, 256>>>(wih1, wih1h, wih1l, H_, 4*H_*H_);
    split_gate_kernel<<<(4*H_*H_ + 255)/256, 256>>>(whh1, whh1h, whh1l, H_, 4*H_*H_);
    split_kernel<<<(H_*H_ + 255)/256, 256>>>(opW1, oW1h, oW1l, H_*H_);
    split_kernel<<<(L_*H_ + 255)/256, 256>>>(opW2, oW2h, oW2l, L_*H_);

    // ---- prologue (fp32) ----
    gemm_small(cs, L_, qW, L_, L_,  nullptr,0,nullptr,0,0, qb,nullptr, q,  H_, B_, H_, 0);
    gemm_small(mem,H_, kW, H_, H_,  nullptr,0,nullptr,0,0, kb,nullptr, km, H_, S_, H_, 0);
    gemm_small(mem,H_, vW, H_, H_,  nullptr,0,nullptr,0,0, vb,nullptr, vm, H_, S_, H_, 0);
    attn_kernel<<<B_, 256>>>(q, km, vm, ctx);
    gemm_small(ctx,H_, moW,H_, H_,  nullptr,0,nullptr,0,0, mob,nullptr, cxt, L_, B_, L_, 0);
    gemm_small(cs, L_, pgW1,      2*L_, L_,
               cxt,L_, pgW1 + L_, 2*L_, L_,
               pgb1, nullptr, pgh, H_, B_, H_, 1);
    gemm_small(pgh,H_, pgW2,H_, H_, nullptr,0,nullptr,0,0, pgb2,nullptr,
               priorbuf, L_, B_, L_, 0);
    split_kernel<<<(B_*L_ + 255)/256, 256>>>(priorbuf, xh, xl, B_*L_);

    // ---- persistent rollout: ONE kernel, 4 phases/step, 256 CTAs x 256 thr --
    rollout_kernel<<<256, 256, P_SMEM>>>(bih0, bhh0, bih1, bhh1, opb1, opb2, out);
}

// round 14
// speedup vs baseline: 1.3497x; 1.2224x over previous
#include <cuda_runtime.h>
#include <cuda_fp16.h>
#include <math.h>
#include <stdint.h>

#define B_ 256
#define L_ 512
#define H_ 1024
#define S_ 16
#define HOR_ 64
#define PRED_ELEMS (B_*HOR_*L_)

typedef __half f16;

// ---------------- fp32 scratch ----------------------------------------------
__device__ float g_q[B_*H_];
__device__ float g_kmem[S_*H_];
__device__ float g_vmem[S_*H_];
__device__ float g_ctx[B_*H_];
__device__ float g_context[B_*L_];
__device__ float g_pgh[B_*H_];
__device__ float g_prior[B_*L_];
__device__ float g_c0[B_*H_];
__device__ float g_c1[B_*H_];

// ---------------- fp16 scratch ------------------------------------------------
// activations: hi/lo split (exact). weights: single fp16 (quantized).
__device__ __align__(16) f16 g_xh[B_*L_],  g_xl[B_*L_];
__device__ __align__(16) f16 g_h0h[2][B_*H_], g_h0l[2][B_*H_];
__device__ __align__(16) f16 g_h1h[2][B_*H_], g_h1l[2][B_*H_];
__device__ __align__(16) f16 g_th[B_*H_],  g_tl[B_*H_];
__device__ __align__(16) f16 g_wih0[4*H_*L_];
__device__ __align__(16) f16 g_whh0[4*H_*H_];
__device__ __align__(16) f16 g_wih1[4*H_*H_];
__device__ __align__(16) f16 g_whh1[4*H_*H_];
__device__ __align__(16) f16 g_opW1[H_*H_];
__device__ __align__(16) f16 g_opW2[L_*H_];

// ---------------- hierarchical grid barrier (256 CTAs: 8 x 32) ---------------
__device__ unsigned g_cnt[8*32];
__device__ unsigned g_cnt2 = 0;
__device__ unsigned g_gen  = 0;

// ---------------- low-level helpers ------------------------------------------
__device__ __forceinline__ uint32_t smem_u32(const void* p) {
    uint32_t a;
    asm("{ .reg .u64 t; cvta.to.shared.u64 t, %1; cvt.u32.u64 %0, t; }" : "=r"(a) : "l"(p));
    return a;
}

#define CP_ASYNC16(d, s) \
    asm volatile("cp.async.cg.shared.global [%0], [%1], 16;" :: "r"(d), "l"(s))
#define CP_COMMIT()  asm volatile("cp.async.commit_group;" ::: "memory")

__device__ __forceinline__ void ldm_x4(uint32_t* r, uint32_t addr) {
    asm volatile("ldmatrix.sync.aligned.m8n8.x4.shared.b16 {%0,%1,%2,%3}, [%4];"
                 : "=r"(r[0]), "=r"(r[1]), "=r"(r[2]), "=r"(r[3]) : "r"(addr));
}

__device__ __forceinline__ void mma16816(float* d, const uint32_t* a, const uint32_t* b) {
    asm volatile(
        "mma.sync.aligned.m16n8k16.row.col.f32.f16.f16.f32 "
        "{%0,%1,%2,%3}, {%4,%5,%6,%7}, {%8,%9}, {%0,%1,%2,%3};"
        : "+f"(d[0]), "+f"(d[1]), "+f"(d[2]), "+f"(d[3])
        : "r"(a[0]), "r"(a[1]), "r"(a[2]), "r"(a[3]), "r"(b[0]), "r"(b[1]));
}

__device__ __forceinline__ void grid_sync() {
    __syncthreads();
    if (threadIdx.x == 0) {
        volatile unsigned* genp = (volatile unsigned*)&g_gen;
        const unsigned gen = *genp;
        __threadfence();
        unsigned old = atomicAdd(&g_cnt[(blockIdx.x & 7) * 32], 1u);
        bool flipped = false;
        if (old == 31u) {
            unsigned old2 = atomicAdd(&g_cnt2, 1u);
            if (old2 == 7u) {
                #pragma unroll
                for (int i = 0; i < 8; i++) g_cnt[i * 32] = 0u;
                g_cnt2 = 0u;
                __threadfence();
                *genp = gen + 1u;
                flipped = true;
            }
        }
        if (!flipped) {
            while (*genp == gen) { }
        }
        __threadfence();
    }
    __syncthreads();
}

// ---------------- device GEMM core (dual source, 4 warps as 2x2) -------------
// A split (hi,lo) fp16, W single fp16: acc += Ah@W^T + Al@W^T
#define PSTRIDE 40
#define P_SMEM (3 * (2*64 + 64) * PSTRIDE * 2)   // 46080 (gates 64x64 config)

template<int BM, int BN>
__device__ __forceinline__ void gemm_dual(
    uint32_t sb, int tid,
    const f16* __restrict__ Ah1, const f16* __restrict__ Al1, int lda1,
    const f16* __restrict__ W1, int ldw1, int nc1,
    const f16* __restrict__ Ah2, const f16* __restrict__ Al2, int lda2,
    const f16* __restrict__ W2, int ldw2, int nc2,
    float (&acc)[BM/32][2*(BN/32)][4])
{
    constexpr int MI  = BM / 32;
    constexpr int NJ  = BN / 32;
    constexpr int AHo = 0;
    constexpr int ALo = BM * PSTRIDE;
    constexpr int Wo  = 2 * BM * PSTRIDE;
    constexpr int STAGE_B = (2 * BM + BN) * PSTRIDE * 2;

    const int lane = tid & 31, wid = tid >> 5;
    const int warp_m = wid >> 1, warp_n = wid & 1;
    const int nc = nc1 + nc2;

    auto do_load = [&](int c) {
        const int src = (c < nc1) ? 0 : 1;
        const int k0  = ((src == 0) ? c : (c - nc1)) << 5;
        const f16* Ah = src ? Ah2 : Ah1;
        const f16* Al = src ? Al2 : Al1;
        const f16* W  = src ? W2  : W1;
        const int lda = src ? lda2 : lda1;
        const int ldw = src ? ldw2 : ldw1;
        const uint32_t st = sb + (uint32_t)(c % 3) * STAGE_B;

        constexpr int T16 = (2 * BM + BN) * 4;
        #pragma unroll
        for (int it = 0; it < T16 / 128; it++) {
            int idx = tid + it * 128;
            int row = idx >> 2, ch = idx & 3;
            const f16* g; int soff;
            if (row < BM)        {               g = Ah + (size_t)row * lda; soff = AHo + row * PSTRIDE; }
            else if (row < 2*BM) { int r = row - BM;   g = Al + (size_t)r * lda; soff = ALo + r * PSTRIDE; }
            else                 { int r = row - 2*BM; g = W  + (size_t)r * ldw; soff = Wo  + r * PSTRIDE; }
            CP_ASYNC16(st + (uint32_t)(soff + ch * 8) * 2, g + k0 + ch * 8);
        }
        CP_COMMIT();
    };

    do_load(0);
    if (nc > 1) do_load(1);

    const int a_row = warp_m * (MI * 16) + (lane & 15);
    const int a_kof = (lane >> 4) << 3;
    const int b_row = warp_n * (NJ * 16) + ((lane >> 4) << 3) + (lane & 7);
    const int b_kof = ((lane >> 3) & 1) << 3;

    for (int c = 0; c < nc; c++) {
        if (c + 1 < nc) asm volatile("cp.async.wait_group 1;" ::: "memory");
        else            asm volatile("cp.async.wait_group 0;" ::: "memory");
        __syncthreads();

        if (c + 2 < nc) do_load(c + 2);

        const uint32_t st = sb + (uint32_t)(c % 3) * STAGE_B;

        #pragma unroll
        for (int k16 = 0; k16 < 2; k16++) {
            const int kk = k16 * 16;
            uint32_t ah[MI][4], al[MI][4], bw[NJ][4];
            #pragma unroll
            for (int mi = 0; mi < MI; mi++) {
                ldm_x4(ah[mi], st + (uint32_t)((AHo + (a_row + mi*16) * PSTRIDE + kk + a_kof) * 2));
                ldm_x4(al[mi], st + (uint32_t)((ALo + (a_row + mi*16) * PSTRIDE + kk + a_kof) * 2));
            }
            #pragma unroll
            for (int g = 0; g < NJ; g++)
                ldm_x4(bw[g], st + (uint32_t)((Wo + (b_row + g*16) * PSTRIDE + kk + b_kof) * 2));
            #pragma unroll
            for (int mi = 0; mi < MI; mi++)
                #pragma unroll
                for (int nj = 0; nj < 2*NJ; nj++) {
                    const int g = nj >> 1, o = (nj & 1) * 2;
                    mma16816(acc[mi][nj], ah[mi], &bw[g][o]);
                    mma16816(acc[mi][nj], al[mi], &bw[g][o]);
                }
        }
    }
    __syncthreads();
}

template<int MI, int NJ2>
__device__ __forceinline__ void zero_acc(float (&acc)[MI][NJ2][4]) {
    #pragma unroll
    for (int i = 0; i < MI; i++)
        #pragma unroll
        for (int j = 0; j < NJ2; j++)
            #pragma unroll
            for (int r = 0; r < 4; r++) acc[i][j][r] = 0.f;
}

// fused LSTM cell epilogue (64x64 tiles, warp 32x32; col n = 4*j + gate)
__device__ __forceinline__ void cell_epi(
    float (&acc)[2][4][4], int tid, int m0, int n0,
    const float* __restrict__ b1, const float* __restrict__ b2,
    const float* __restrict__ cin, float* __restrict__ cout,
    f16* __restrict__ Oh, f16* __restrict__ Ol)
{
    const int lane = tid & 31, wid = tid >> 5;
    const int warp_m = wid >> 1, warp_n = wid & 1;
    const int m_base = m0 + warp_m * 32;
    const int n_base = n0 + warp_n * 32;
    #pragma unroll
    for (int mi = 0; mi < 2; mi++) {
        #pragma unroll
        for (int nj = 0; nj < 4; nj++) {
            const int c0 = n_base + nj * 8 + (lane & 3) * 2;
            const int bi0 = (c0 & 3) * H_ + (c0 >> 2);
            const int bi1 = ((c0 + 1) & 3) * H_ + ((c0 + 1) >> 2);
            const float bias0 = b1[bi0] + b2[bi0];
            const float bias1 = b1[bi1] + b2[bi1];
            #pragma unroll
            for (int half = 0; half < 2; half++) {
                const int row = m_base + mi * 16 + (lane >> 2) + half * 8;
                float v0 = acc[mi][nj][half*2 + 0] + bias0;
                float v1 = acc[mi][nj][half*2 + 1] + bias1;
                float p0 = __shfl_xor_sync(0xffffffffu, v0, 1);
                float p1 = __shfl_xor_sync(0xffffffffu, v1, 1);
                if ((lane & 1) == 0) {
                    const int j   = c0 >> 2;
                    const int idx = row * H_ + j;
                    float ig = 1.f / (1.f + expf(-v0));
                    float fg = 1.f / (1.f + expf(-v1));
                    float gg = tanhf(p0);
                    float og = 1.f / (1.f + expf(-p1));
                    float cv = fg * cin[idx] + ig * gg;
                    float hv = og * tanhf(cv);
                    cout[idx] = cv;
                    f16 hb = __float2half(hv);
                    Oh[idx] = hb;
                    Ol[idx] = __float2half(hv - __half2float(hb));
                }
            }
        }
    }
}

// standard epilogue: bias (+relu), optional fp32 C, optional fp16 hi/lo split
template<int MI, int NJ>
__device__ __forceinline__ void std_epi(
    float (&acc)[MI][2*NJ][4], int tid, int m0, int n0,
    const float* __restrict__ b,
    float* __restrict__ C, int ldc,
    f16* __restrict__ Oh, f16* __restrict__ Ol, int ldo, int relu)
{
    const int lane = tid & 31, wid = tid >> 5;
    const int warp_m = wid >> 1, warp_n = wid & 1;
    const int m_base = m0 + warp_m * (MI * 16);
    const int n_base = n0 + warp_n * (NJ * 16);
    #pragma unroll
    for (int mi = 0; mi < MI; mi++) {
        #pragma unroll
        for (int nj = 0; nj < 2*NJ; nj++) {
            const int col = n_base + nj * 8 + (lane & 3) * 2;
            const float bias0 = b[col];
            const float bias1 = b[col + 1];
            #pragma unroll
            for (int half = 0; half < 2; half++) {
                const int row = m_base + mi * 16 + (lane >> 2) + half * 8;
                float v0 = acc[mi][nj][half*2 + 0] + bias0;
                float v1 = acc[mi][nj][half*2 + 1] + bias1;
                if (relu) { v0 = fmaxf(v0, 0.f); v1 = fmaxf(v1, 0.f); }
                if (C)
                    *reinterpret_cast<float2*>(C + (size_t)row * ldc + col) =
                        make_float2(v0, v1);
                if (Oh) {
                    f16 h0 = __float2half(v0);
                    f16 h1 = __float2half(v1);
                    f16 l0 = __float2half(v0 - __half2float(h0));
                    f16 l1 = __float2half(v1 - __half2float(h1));
                    f16 hp[2] = {h0, h1}, lp[2] = {l0, l1};
                    *reinterpret_cast<uint32_t*>(Oh + (size_t)row * ldo + col) =
                        *reinterpret_cast<uint32_t*>(hp);
                    *reinterpret_cast<uint32_t*>(Ol + (size_t)row * ldo + col) =
                        *reinterpret_cast<uint32_t*>(lp);
                }
            }
        }
    }
}

// ---------------- persistent rollout kernel ----------------------------------
__global__ void __launch_bounds__(128, 2)
rollout_kernel(const float* __restrict__ bih0, const float* __restrict__ bhh0,
               const float* __restrict__ bih1, const float* __restrict__ bhh1,
               const float* __restrict__ opb1, const float* __restrict__ opb2,
               float* __restrict__ out)
{
    extern __shared__ __align__(16) char smem[];
    const uint32_t sb = smem_u32(smem);
    const int tid = threadIdx.x;
    const int cta = blockIdx.x;

    const int gm0 = (cta & 3) * 64;
    const int gn0 = (cta >> 2) * 64;
    const int o1m = (cta & 7) * 32, o1n = (cta >> 3) * 32;
    const int o2m = (cta & 7) * 32, o2n = (cta >> 3) * 32;

    for (int s = 0; s < HOR_; s++) {
        const int p = s & 1, pn = p ^ 1;

        // ---- phase 1: gates0 (x@wih0 + h0@whh0) + cell -> h0[pn], c0 ----
        {
            float acc[2][4][4];
            zero_acc(acc);
            gemm_dual<64,64>(sb, tid,
                g_xh + (size_t)gm0*L_, g_xl + (size_t)gm0*L_, L_,
                g_wih0 + (size_t)gn0*L_, L_, L_/32,
                g_h0h[p] + (size_t)gm0*H_, g_h0l[p] + (size_t)gm0*H_, H_,
                g_whh0 + (size_t)gn0*H_, H_, H_/32,
                acc);
            cell_epi(acc, tid, gm0, gn0, bih0, bhh0, g_c0, g_c0, g_h0h[pn], g_h0l[pn]);
        }
        grid_sync();

        // ---- phase 2: gates1 (h0@wih1 + h1@whh1) + cell -> h1[pn], c1 ----
        {
            float acc[2][4][4];
            zero_acc(acc);
            gemm_dual<64,64>(sb, tid,
                g_h0h[pn] + (size_t)gm0*H_, g_h0l[pn] + (size_t)gm0*H_, H_,
                g_wih1 + (size_t)gn0*H_, H_, H_/32,
                g_h1h[p] + (size_t)gm0*H_, g_h1l[p] + (size_t)gm0*H_, H_,
                g_whh1 + (size_t)gn0*H_, H_, H_/32,
                acc);
            cell_epi(acc, tid, gm0, gn0, bih1, bhh1, g_c1, g_c1, g_h1h[pn], g_h1l[pn]);
        }
        grid_sync();

        // ---- phase 3: op1 = relu(h1 @ opW1^T + b1) -> th/tl  (32x32, 256 CTAs)
        {
            float acc[1][2][4];
            zero_acc(acc);
            gemm_dual<32,32>(sb, tid,
                g_h1h[pn] + (size_t)o1m*H_, g_h1l[pn] + (size_t)o1m*H_, H_,
                g_opW1 + (size_t)o1n*H_, H_, H_/32,
                nullptr, nullptr, 0, nullptr, 0, 0,
                acc);
            std_epi<1,1>(acc, tid, o1m, o1n, opb1, nullptr, 0, g_th, g_tl, H_, 1);
        }
        grid_sync();

        // ---- phase 4: op2 = t @ opW2^T + b2 -> out + x split (32x32, 128 CTAs)
        if (cta < 128) {
            float acc[1][2][4];
            zero_acc(acc);
            gemm_dual<32,32>(sb, tid,
                g_th + (size_t)o2m*H_, g_tl + (size_t)o2m*H_, H_,
                g_opW2 + (size_t)o2n*H_, H_, H_/32,
                nullptr, nullptr, 0, nullptr, 0, 0,
                acc);
            std_epi<1,1>(acc, tid, o2m, o2n, opb2,
                         out + (size_t)s * L_, HOR_*L_, g_xh, g_xl, L_, 0);
        }
        grid_sync();
    }
}

// ---------------- fp32 GEMM (prologue only) ---------------------------------
template<int BM,int BN,int BK,int TM,int TN,int NT>
__global__ __launch_bounds__(NT)
void gemm2_kernel(const float* __restrict__ A1, int lda1,
                  const float* __restrict__ W1, int ldw1, int K1,
                  const float* __restrict__ A2, int lda2,
                  const float* __restrict__ W2, int ldw2, int K2,
                  const float* __restrict__ b1, const float* __restrict__ b2,
                  float* __restrict__ C, int ldc, int M, int N, int relu)
{
    __shared__ __align__(16) float As[BK][BM+4];
    __shared__ __align__(16) float Ws[BK][BN+4];
    const int tid = threadIdx.x;
    const int m0  = blockIdx.y * BM;
    const int n0  = blockIdx.x * BN;
    const int m0t = (tid / (BN/TN)) * TM;
    const int n0t = (tid % (BN/TN)) * TN;
    float acc[TM][TN];
    #pragma unroll
    for (int i = 0; i < TM; i++)
        #pragma unroll
        for (int j = 0; j < TN; j++) acc[i][j] = 0.f;
    for (int src = 0; src < 2; src++) {
        const float* A = src ? A2 : A1;
        if (A == nullptr) break;
        const float* W = src ? W2 : W1;
        const int lda = src ? lda2 : lda1;
        const int ldw = src ? ldw2 : ldw1;
        const int K   = src ? K2   : K1;
        for (int k0 = 0; k0 < K; k0 += BK) {
            constexpr int A4 = BM*BK/4;
            #pragma unroll
            for (int it = 0; it < A4/NT; it++) {
                int i4 = tid + NT*it;
                int row = i4 / (BK/4), cv = i4 % (BK/4);
                float4 val = make_float4(0,0,0,0);
                int gr = m0 + row;
                if (gr < M) val = *reinterpret_cast<const float4*>(A + (size_t)gr*lda + k0 + cv*4);
                As[cv*4+0][row]=val.x; As[cv*4+1][row]=val.y;
                As[cv*4+2][row]=val.z; As[cv*4+3][row]=val.w;
            }
            constexpr int W4 = BN*BK/4;
            #pragma unroll
            for (int it = 0; it < W4/NT; it++) {
                int i4 = tid + NT*it;
                int row = i4 / (BK/4), cv = i4 % (BK/4);
                float4 val = *reinterpret_cast<const float4*>(W + (size_t)(n0+row)*ldw + k0 + cv*4);
                Ws[cv*4+0][row]=val.x; Ws[cv*4+1][row]=val.y;
                Ws[cv*4+2][row]=val.z; Ws[cv*4+3][row]=val.w;
            }
            __syncthreads();
            #pragma unroll
            for (int kk = 0; kk < BK; kk++) {
                float a[TM], bb[TN];
                #pragma unroll
                for (int i = 0; i < TM; i += 4) {
                    float4 t = *reinterpret_cast<const float4*>(&As[kk][m0t+i]);
                    a[i]=t.x; a[i+1]=t.y; a[i+2]=t.z; a[i+3]=t.w;
                }
                #pragma unroll
                for (int j = 0; j < TN; j += 4) {
                    float4 t = *reinterpret_cast<const float4*>(&Ws[kk][n0t+j]);
                    bb[j]=t.x; bb[j+1]=t.y; bb[j+2]=t.z; bb[j+3]=t.w;
                }
                #pragma unroll
                for (int i = 0; i < TM; i++)
                    #pragma unroll
                    for (int j = 0; j < TN; j++)
                        acc[i][j] = fmaf(a[i], bb[j], acc[i][j]);
            }
            __syncthreads();
        }
    }
    #pragma unroll
    for (int j = 0; j < TN; j++) {
        int gn = n0 + n0t + j;
        float bias = (b1 ? b1[gn] : 0.f) + (b2 ? b2[gn] : 0.f);
        #pragma unroll
        for (int i = 0; i < TM; i++) {
            int gm = m0 + m0t + i;
            if (gm < M) {
                float vo = acc[i][j] + bias;
                if (relu) vo = fmaxf(vo, 0.f);
                C[(size_t)gm*ldc + gn] = vo;
            }
        }
    }
}

// ---------------- attention --------------------------------------------------
__global__ __launch_bounds__(256)
void attn_kernel(const float* __restrict__ q, const float* __restrict__ k,
                 const float* __restrict__ v, float* __restrict__ ctx)
{
    const int b = blockIdx.x, tid = threadIdx.x;
    const int lane = tid & 31, wid = tid >> 5;
    float p[S_];
    #pragma unroll
    for (int s = 0; s < S_; s++) p[s] = 0.f;
    for (int e = tid; e < H_; e += 256) {
        float qv = q[b*H_ + e];
        #pragma unroll
        for (int s = 0; s < S_; s++) p[s] = fmaf(qv, k[s*H_ + e], p[s]);
    }
    #pragma unroll
    for (int s = 0; s < S_; s++)
        #pragma unroll
        for (int off = 16; off > 0; off >>= 1)
            p[s] += __shfl_down_sync(0xffffffffu, p[s], off);
    __shared__ float sred[S_*8];
    __shared__ float wts[S_];
    if (lane == 0)
        #pragma unroll
        for (int s = 0; s < S_; s++) sred[s*8 + wid] = p[s];
    __syncthreads();
    if (tid == 0) {
        float sc[S_]; float mx = -1e30f;
        #pragma unroll
        for (int s = 0; s < S_; s++) {
            float a = 0.f;
            #pragma unroll
            for (int w = 0; w < 8; w++) a += sred[s*8 + w];
            sc[s] = a * (1.0f/32.0f);
            mx = fmaxf(mx, sc[s]);
        }
        float sum = 0.f;
        #pragma unroll
        for (int s = 0; s < S_; s++) { sc[s] = expf(sc[s]-mx); sum += sc[s]; }
        float inv = 1.f/sum;
        #pragma unroll
        for (int s = 0; s < S_; s++) wts[s] = sc[s]*inv;
    }
    __syncthreads();
    for (int j = tid; j < H_; j += 256) {
        float a = 0.f;
        #pragma unroll
        for (int s = 0; s < S_; s++) a = fmaf(wts[s], v[s*H_ + j], a);
        ctx[b*H_ + j] = a;
    }
}

// ---------------- converts ------------------------------------------------------
// fp32 -> fp16 hi/lo split (activations; exact to 2^-22)
__global__ __launch_bounds__(256)
void split_kernel(const float* __restrict__ src, f16* __restrict__ hi,
                  f16* __restrict__ lo, int n)
{
    int i = blockIdx.x*blockDim.x + threadIdx.x;
    if (i < n) {
        float v = src[i];
        f16 h = __float2half(v);
        hi[i] = h;
        lo[i] = __float2half(v - __half2float(h));
    }
}

// gate-interleaved fp16 weight convert: out row n = 4*j + g <- in row g*H + j
__global__ __launch_bounds__(256)
void conv_gate_kernel(const float* __restrict__ src, f16* __restrict__ dst,
                      int K, int n)
{
    int i = blockIdx.x*blockDim.x + threadIdx.x;
    if (i < n) {
        int row = i / K, k = i - row * K;
        int orow = (row & 3) * H_ + (row >> 2);
        dst[i] = __float2half(src[(size_t)orow * K + k]);
    }
}

// plain fp16 weight convert
__global__ __launch_bounds__(256)
void conv_kernel(const float* __restrict__ src, f16* __restrict__ dst, int n)
{
    int i = blockIdx.x*blockDim.x + threadIdx.x;
    if (i < n) dst[i] = __float2half(src[i]);
}

__global__ __launch_bounds__(256)
void zero_state_kernel()
{
    int i = blockIdx.x*blockDim.x + threadIdx.x;
    if (i < B_*H_) {
        g_c0[i] = 0.f; g_c1[i] = 0.f;
        f16 z = __float2half(0.f);
        g_h0h[0][i] = z; g_h0l[0][i] = z; g_h1h[0][i] = z; g_h1l[0][i] = z;
        g_h0h[1][i] = z; g_h0l[1][i] = z; g_h1h[1][i] = z; g_h1l[1][i] = z;
    }
    if (i < 8*32) g_cnt[i] = 0;
    if (i == 0) { g_cnt2 = 0; g_gen = 0; }
}

// ---------------- host helpers -------------------------------------------------
static inline void gemm_small(const float* A1,int lda1,const float* W1,int ldw1,int K1,
                              const float* A2,int lda2,const float* W2,int ldw2,int K2,
                              const float* b1,const float* b2,
                              float* C,int ldc,int M,int N,int relu)
{
    dim3 grid(N/32, (M + 63)/64);
    gemm2_kernel<64,32,16,4,4,128><<<grid,128>>>(A1,lda1,W1,ldw1,K1,
                                                 A2,lda2,W2,ldw2,K2,
                                                 b1,b2,C,ldc,M,N,relu);
}

extern "C" void kernel_launch(void* const* d_in, const int* in_sizes, int n_in,
                              void* d_out, int out_size)
{
    (void)in_sizes; (void)n_in;
    const float* cs   = (const float*)d_in[0];
    const float* mem  = (const float*)d_in[2];
    const float* qW   = (const float*)d_in[3];
    const float* qb   = (const float*)d_in[4];
    const float* kW   = (const float*)d_in[5];
    const float* kb   = (const float*)d_in[6];
    const float* vW   = (const float*)d_in[7];
    const float* vb   = (const float*)d_in[8];
    const float* moW  = (const float*)d_in[9];
    const float* mob  = (const float*)d_in[10];
    const float* pgW1 = (const float*)d_in[11];
    const float* pgb1 = (const float*)d_in[12];
    const float* pgW2 = (const float*)d_in[13];
    const float* pgb2 = (const float*)d_in[14];
    const float* wih0 = (const float*)d_in[15];
    const float* whh0 = (const float*)d_in[16];
    const float* bih0 = (const float*)d_in[17];
    const float* bhh0 = (const float*)d_in[18];
    const float* wih1 = (const float*)d_in[19];
    const float* whh1 = (const float*)d_in[20];
    const float* bih1 = (const float*)d_in[21];
    const float* bhh1 = (const float*)d_in[22];
    const float* opW1 = (const float*)d_in[23];
    const float* opb1 = (const float*)d_in[24];
    const float* opW2 = (const float*)d_in[25];
    const float* opb2 = (const float*)d_in[26];

    float* out = (float*)d_out;

    cudaFuncSetAttribute(rollout_kernel, cudaFuncAttributeMaxDynamicSharedMemorySize, P_SMEM);

    // scratch addresses
    float *q,*km,*vm,*ctx,*cxt,*pgh,*prior_s;
    cudaGetSymbolAddress((void**)&q, g_q);
    cudaGetSymbolAddress((void**)&km, g_kmem);
    cudaGetSymbolAddress((void**)&vm, g_vmem);
    cudaGetSymbolAddress((void**)&ctx, g_ctx);
    cudaGetSymbolAddress((void**)&cxt, g_context);
    cudaGetSymbolAddress((void**)&pgh, g_pgh);
    cudaGetSymbolAddress((void**)&prior_s, g_prior);

    f16 *xh,*xl,*w0,*wh0,*w1,*wh1,*ow1,*ow2;
    cudaGetSymbolAddress((void**)&xh, g_xh);   cudaGetSymbolAddress((void**)&xl, g_xl);
    cudaGetSymbolAddress((void**)&w0, g_wih0);  cudaGetSymbolAddress((void**)&wh0, g_whh0);
    cudaGetSymbolAddress((void**)&w1, g_wih1);  cudaGetSymbolAddress((void**)&wh1, g_whh1);
    cudaGetSymbolAddress((void**)&ow1, g_opW1); cudaGetSymbolAddress((void**)&ow2, g_opW2);

    bool has_prior_region = (out_size >= PRED_ELEMS + B_*L_);
    float* priorbuf = has_prior_region ? (out + PRED_ELEMS) : prior_s;

    // ---- state init + weight conversion (gate weights permuted to 4j+g order)
    zero_state_kernel<<<(B_*H_ + 255)/256, 256>>>();
    conv_gate_kernel<<<(4*H_*L_ + 255)/256, 256>>>(wih0, w0, L_, 4*H_*L_);
    conv_gate_kernel<<<(4*H_*H_ + 255)/256, 256>>>(whh0, wh0, H_, 4*H_*H_);
    conv_gate_kernel<<<(4*H_*H_ + 255)/256, 256>>>(wih1, w1, H_, 4*H_*H_);
    conv_gate_kernel<<<(4*H_*H_ + 255)/256, 256>>>(whh1, wh1, H_, 4*H_*H_);
    conv_kernel<<<(H_*H_ + 255)/256, 256>>>(opW1, ow1, H_*H_);
    conv_kernel<<<(L_*H_ + 255)/256, 256>>>(opW2, ow2, L_*H_);

    // ---- prologue (fp32) ----
    gemm_small(cs, L_, qW, L_, L_,  nullptr,0,nullptr,0,0, qb,nullptr, q,  H_, B_, H_, 0);
    gemm_small(mem,H_, kW, H_, H_,  nullptr,0,nullptr,0,0, kb,nullptr, km, H_, S_, H_, 0);
    gemm_small(mem,H_, vW, H_, H_,  nullptr,0,nullptr,0,0, vb,nullptr, vm, H_, S_, H_, 0);
    attn_kernel<<<B_, 256>>>(q, km, vm, ctx);
    gemm_small(ctx,H_, moW,H_, H_,  nullptr,0,nullptr,0,0, mob,nullptr, cxt, L_, B_, L_, 0);
    gemm_small(cs, L_, pgW1,      2*L_, L_,
               cxt,L_, pgW1 + L_, 2*L_, L_,
               pgb1, nullptr, pgh, H_, B_, H_, 1);
    gemm_small(pgh,H_, pgW2,H_, H_, nullptr,0,nullptr,0,0, pgb2,nullptr,
               priorbuf, L_, B_, L_, 0);
    split_kernel<<<(B_*L_ + 255)/256, 256>>>(priorbuf, xh, xl, B_*L_);

    // ---- persistent rollout: ONE kernel, 4 phases/step ----
    rollout_kernel<<<256, 128, P_SMEM>>>(bih0, bhh0, bih1, bhh1, opb1, opb2, out);
}